// round 9
// baseline (speedup 1.0000x reference)
#include <cuda_runtime.h>
#include <cuda_bf16.h>
#include <math.h>

#define T_LEN 4096
#define S 5
#define AL 4
#define GROUP 8
#define NG (T_LEN / GROUP)

// Fixed boundary: fwd warps zero [texit, T0) themselves; [T0, T) is a static
// region filled concurrently by fill-role CTAs in the same launch.
#define T0 512
#define F4_PER_ROW (T_LEN * S / 4)          // 5120 float4 per row
#define F4_T0 (T0 * S / 4)                  // 640: f4 index where static region starts
#define F4_STATIC (F4_PER_ROW - F4_T0)      // 4480 f4 per row in static region
#define CHUNK 64                             // f4 per fill chunk (1 KB)
#define CHUNKS_PER_ROW (F4_STATIC / CHUNK)   // 70

#define FWD_THREADS 64                       // 2 warps per fwd CTA
#define FILL_CTAS 1120

__device__ __forceinline__ void load_group(float4 (&buf)[GROUP],
                                           const float4* __restrict__ xb, int g) {
    #pragma unroll
    for (int k = 0; k < GROUP; k++) buf[k] = xb[g * GROUP + k];
}

__device__ __forceinline__ void compute_group(const float4 (&buf)[GROUP],
                                              float (&al)[S],
                                              const float (&A_)[S][S],
                                              const float (&Bm)[S][AL],
                                              float* __restrict__ ob,
                                              int g, bool valid) {
    #pragma unroll
    for (int h = 0; h < 2; h++) {
        float st[4 * S];
        #pragma unroll
        for (int q = 0; q < 4; q++) {
            const int k = h * 4 + q;
            float4 v = buf[k];
            if (g == 0 && k == 0) {
                // t = 0: alpha0 = [E(b,0,0), 0, 0, 0, 0]
                al[0] = fmaf(Bm[0][3], v.w, fmaf(Bm[0][2], v.z,
                         fmaf(Bm[0][1], v.y, Bm[0][0] * v.x)));
                #pragma unroll
                for (int j = 1; j < S; j++) al[j] = 0.f;
            } else {
                float e[S], ns[S];
                #pragma unroll
                for (int j = 0; j < S; j++)
                    e[j] = fmaf(Bm[j][3], v.w, fmaf(Bm[j][2], v.z,
                             fmaf(Bm[j][1], v.y, Bm[j][0] * v.x)));
                #pragma unroll
                for (int j = 0; j < S; j++) {
                    float s01 = fmaf(al[1], A_[1][j], al[0] * A_[0][j]);
                    float s23 = fmaf(al[3], A_[3][j], al[2] * A_[2][j]);
                    float sm  = fmaf(al[4], A_[4][j], s01 + s23);
                    ns[j] = e[j] * sm;
                }
                #pragma unroll
                for (int j = 0; j < S; j++) al[j] = ns[j];
            }
            #pragma unroll
            for (int j = 0; j < S; j++) st[q * S + j] = al[j];
        }
        if (valid) {
            float4* op = reinterpret_cast<float4*>(ob + (size_t)(g * GROUP + h * 4) * S);
            #pragma unroll
            for (int q = 0; q < 5; q++)
                op[q] = make_float4(st[q * 4 + 0], st[q * 4 + 1],
                                    st[q * 4 + 2], st[q * 4 + 3]);
        }
    }
}

__device__ __forceinline__ bool alpha_zero(const float (&al)[S]) {
    float s = fabsf(al[0]) + fabsf(al[1]) + fabsf(al[2]) + fabsf(al[3]) + fabsf(al[4]);
    return s == 0.0f;
}

// Fused kernel. Bids [0, nFwd): forward recurrence, 1 thread per row, register
// double-buffered prefetch; after warp-uniform underflow each warp zeroes
// [texit, T0) for its 32 rows. Bids [nFwd, ...): coalesced zero-fill of the
// static region [T0, T) for all rows — independent of texit, so it runs
// concurrently with the recurrence instead of after it.
__global__ void __launch_bounds__(FWD_THREADS)
hmm_fused(const float4* __restrict__ x,
          const float* __restrict__ tk,
          const float* __restrict__ ek,
          float* __restrict__ out, int B, int nFwd) {
    int bid = blockIdx.x;
    int tid = threadIdx.x;

    if (bid >= nFwd) {
        // ---- static fill role: zero out[:, T0:, :] ----
        int nChunks = B * CHUNKS_PER_ROW;
        int nFillCtas = gridDim.x - nFwd;
        float4 z4 = make_float4(0.f, 0.f, 0.f, 0.f);
        for (int c = bid - nFwd; c < nChunks; c += nFillCtas) {
            int row = c / CHUNKS_PER_ROW;
            int cof = c % CHUNKS_PER_ROW;
            float4* p = reinterpret_cast<float4*>(out) +
                        (size_t)row * F4_PER_ROW + F4_T0 + cof * CHUNK;
            p[tid] = z4;
        }
        return;
    }

    // ---- forward role ----
    __shared__ float sA[S * S];
    __shared__ float sB[S * AL];

    if (tid < S) {
        float r[S];
        float m = -1e30f;
        #pragma unroll
        for (int j = 0; j < S; j++) { r[j] = tk[tid * S + j]; m = fmaxf(m, r[j]); }
        float s = 0.f;
        #pragma unroll
        for (int j = 0; j < S; j++) { r[j] = expf(r[j] - m); s += r[j]; }
        float inv = 1.0f / s;
        #pragma unroll
        for (int j = 0; j < S; j++) sA[tid * S + j] = r[j] * inv;

        float q[AL];
        m = -1e30f;
        #pragma unroll
        for (int j = 0; j < AL; j++) { q[j] = ek[tid * AL + j]; m = fmaxf(m, q[j]); }
        s = 0.f;
        #pragma unroll
        for (int j = 0; j < AL; j++) { q[j] = expf(q[j] - m); s += q[j]; }
        inv = 1.0f / s;
        #pragma unroll
        for (int j = 0; j < AL; j++) sB[tid * AL + j] = q[j] * inv;
    }
    __syncthreads();

    int row = bid * FWD_THREADS + tid;
    bool valid = row < B;
    int r = valid ? row : (B > 0 ? B - 1 : 0);

    float A_[S][S], Bm[S][AL];
    #pragma unroll
    for (int i = 0; i < S; i++) {
        #pragma unroll
        for (int j = 0; j < S; j++) A_[i][j] = sA[i * S + j];
        #pragma unroll
        for (int a = 0; a < AL; a++) Bm[i][a] = sB[i * AL + a];
    }

    const float4* xb = x + (size_t)r * T_LEN;
    float* ob = out + (size_t)r * T_LEN * S;

    float al[S];
    #pragma unroll
    for (int j = 0; j < S; j++) al[j] = 0.f;

    float4 bufA[GROUP], bufB[GROUP];
    load_group(bufA, xb, 0);

    int texit = T_LEN;
    for (int gp = 0; gp < NG; gp += 2) {
        load_group(bufB, xb, gp + 1);
        compute_group(bufA, al, A_, Bm, ob, gp, valid);
        bool z = !valid || alpha_zero(al);
        if (__all_sync(0xffffffffu, z)) { texit = (gp + 1) * GROUP; break; }

        if (gp + 2 < NG) load_group(bufA, xb, gp + 2);
        compute_group(bufB, al, A_, Bm, ob, gp + 1, valid);
        z = !valid || alpha_zero(al);
        if (__all_sync(0xffffffffu, z)) { texit = (gp + 2) * GROUP; break; }
    }

    // ---- dynamic tail: zero [texit, T0) for this warp's 32 rows ----
    if (texit >= T0) return;  // no underflow before T0 (or exactly at it)

    int lane = tid & 31;
    int warpRowBase = bid * FWD_THREADS + (tid & ~31);  // first row of this warp
    int fstart = texit * S / 4;                          // texit mult of 8 -> exact
    #pragma unroll 1
    for (int rr = 0; rr < 32; rr++) {
        int rowf = warpRowBase + rr;
        if (rowf >= B) break;
        float4* p = reinterpret_cast<float4*>(out) + (size_t)rowf * F4_PER_ROW;
        float4 z4 = make_float4(0.f, 0.f, 0.f, 0.f);
        for (int i = fstart + lane; i < F4_T0; i += 32) p[i] = z4;
    }
}

extern "C" void kernel_launch(void* const* d_in, const int* in_sizes, int n_in,
                              void* d_out, int out_size) {
    const float4* x  = (const float4*)d_in[0];   // inputs (B, T, 4) fp32
    const float*  tk = (const float*)d_in[1];    // transition_kernel (5,5)
    const float*  ek = (const float*)d_in[2];    // emission_kernel (5,4)
    float* out = (float*)d_out;                  // alphas (B, T, 5) fp32

    int B = in_sizes[0] / (T_LEN * AL);
    int nFwd = (B + FWD_THREADS - 1) / FWD_THREADS;   // 32 for B=2048
    int grid = nFwd + FILL_CTAS;

    hmm_fused<<<grid, FWD_THREADS>>>(x, tk, ek, out, B, nFwd);
}

// round 12
// speedup vs baseline: 1.1004x; 1.1004x over previous
#include <cuda_runtime.h>
#include <cuda_bf16.h>
#include <cstdint>
#include <math.h>

#define T_LEN 4096
#define S 5
#define AL 4
#define W 8                       // timesteps per window
#define NW (T_LEN / W)            // 512 windows
#define THREADS 128               // rows per fwd CTA == threads
#define NBUF 3                    // cp.async pipeline depth-2 => 3 buffers
#define F4_PER_ROW (T_LEN * S / 4)  // 5120
#define MAXB 8192

// dynamic smem layout (in float4 units):
//   sIn[NBUF][THREADS][9]  (pad 8->9 to break bank conflicts)
//   sOut[THREADS][11]      (10 f4 = 40 floats = 8 steps x 5 states, pad ->11)
#define SIN_IDX(b, r, s) ((((b) * THREADS) + (r)) * 9 + (s))
#define SOUT_BASE (NBUF * THREADS * 9)
#define SOUT_IDX(r, q) (SOUT_BASE + (r) * 11 + (q))
#define SMEM_F4 (SOUT_BASE + THREADS * 11)
#define SMEM_BYTES (SMEM_F4 * 16)

__device__ int g_texit[MAXB];

__device__ __forceinline__ unsigned int smem_u32(const void* p) {
    unsigned int a;
    asm("{ .reg .u64 t; cvta.to.shared.u64 t, %1; cvt.u32.u64 %0, t; }" : "=r"(a) : "l"(p));
    return a;
}

// Stage window w: 128 rows x 8 f4, fully coalesced (8 threads cover one row's
// 128B segment -> 4 lines per LDG, vs 32 lines for the row-per-thread layout).
__device__ __forceinline__ void stage_window(unsigned int sbase,
                                             const float4* __restrict__ x,
                                             int base_row, int B, int w, int tid) {
    int b = w % NBUF;
    #pragma unroll
    for (int k = 0; k < W; k++) {
        int i = tid + THREADS * k;
        int rw = i >> 3;
        int s = i & 7;
        int row = base_row + rw;
        if (row >= B) row = B - 1;           // duplicate load, never stored
        const float4* src = x + (size_t)row * T_LEN + w * W + s;
        unsigned int dst = sbase + (unsigned int)(SIN_IDX(b, rw, s) * 16);
        asm volatile("cp.async.ca.shared.global [%0], [%1], 16;" :: "r"(dst), "l"(src));
    }
    asm volatile("cp.async.commit_group;");
}

__global__ void __launch_bounds__(THREADS)
hmm_fwd(const float4* __restrict__ x,
        const float* __restrict__ tk,
        const float* __restrict__ ek,
        float* __restrict__ out, int B) {
    extern __shared__ float4 dyn[];
    unsigned int sbase = smem_u32(dyn);

    __shared__ float sA[S * S];
    __shared__ float sB[S * AL];

    int tid = threadIdx.x;
    int base_row = blockIdx.x * THREADS;

    if (tid < S) {
        float r[S];
        float m = -1e30f;
        #pragma unroll
        for (int j = 0; j < S; j++) { r[j] = tk[tid * S + j]; m = fmaxf(m, r[j]); }
        float s = 0.f;
        #pragma unroll
        for (int j = 0; j < S; j++) { r[j] = expf(r[j] - m); s += r[j]; }
        float inv = 1.0f / s;
        #pragma unroll
        for (int j = 0; j < S; j++) sA[tid * S + j] = r[j] * inv;

        float q[AL];
        m = -1e30f;
        #pragma unroll
        for (int j = 0; j < AL; j++) { q[j] = ek[tid * AL + j]; m = fmaxf(m, q[j]); }
        s = 0.f;
        #pragma unroll
        for (int j = 0; j < AL; j++) { q[j] = expf(q[j] - m); s += q[j]; }
        inv = 1.0f / s;
        #pragma unroll
        for (int j = 0; j < AL; j++) sB[tid * AL + j] = q[j] * inv;
    }

    // prologue: stage windows 0 and 1 (no barrier needed before cp.async;
    // the sIn buffers are only ever written by cp.async)
    stage_window(sbase, x, base_row, B, 0, tid);
    stage_window(sbase, x, base_row, B, 1, tid);

    __syncthreads();   // sA/sB ready

    int row = base_row + tid;
    bool valid = row < B;

    float A_[S][S], Bm[S][AL];
    #pragma unroll
    for (int i = 0; i < S; i++) {
        #pragma unroll
        for (int j = 0; j < S; j++) A_[i][j] = sA[i * S + j];
        #pragma unroll
        for (int a = 0; a < AL; a++) Bm[i][a] = sB[i * AL + a];
    }

    float4* outf4 = reinterpret_cast<float4*>(out);

    float al[S];
    #pragma unroll
    for (int j = 0; j < S; j++) al[j] = 0.f;

    int texit = T_LEN;

    for (int w = 0; w < NW; w++) {
        asm volatile("cp.async.wait_group 1;" ::: "memory");  // window w resident
        __syncthreads();

        const int b = w % NBUF;

        // ---- compute 8 steps for row `tid` from SMEM, stage outputs to sOut ----
        #pragma unroll
        for (int h = 0; h < 2; h++) {
            float st[4 * S];
            #pragma unroll
            for (int q = 0; q < 4; q++) {
                const int k = h * 4 + q;
                float4 v = dyn[SIN_IDX(b, tid, k)];
                if (w == 0 && k == 0) {
                    // t = 0: alpha0 = [E(b,0,0), 0, 0, 0, 0]
                    al[0] = fmaf(Bm[0][3], v.w, fmaf(Bm[0][2], v.z,
                             fmaf(Bm[0][1], v.y, Bm[0][0] * v.x)));
                    #pragma unroll
                    for (int j = 1; j < S; j++) al[j] = 0.f;
                } else {
                    float e[S], ns[S];
                    #pragma unroll
                    for (int j = 0; j < S; j++)
                        e[j] = fmaf(Bm[j][3], v.w, fmaf(Bm[j][2], v.z,
                                 fmaf(Bm[j][1], v.y, Bm[j][0] * v.x)));
                    #pragma unroll
                    for (int j = 0; j < S; j++) {
                        float s01 = fmaf(al[1], A_[1][j], al[0] * A_[0][j]);
                        float s23 = fmaf(al[3], A_[3][j], al[2] * A_[2][j]);
                        float sm  = fmaf(al[4], A_[4][j], s01 + s23);
                        ns[j] = e[j] * sm;
                    }
                    #pragma unroll
                    for (int j = 0; j < S; j++) al[j] = ns[j];
                }
                #pragma unroll
                for (int j = 0; j < S; j++) st[q * S + j] = al[j];
            }
            // 4 steps x 5 states = 5 float4, step-major == output layout
            #pragma unroll
            for (int q = 0; q < 5; q++)
                dyn[SOUT_IDX(tid, h * 5 + q)] =
                    make_float4(st[q * 4 + 0], st[q * 4 + 1],
                                st[q * 4 + 2], st[q * 4 + 3]);
        }

        float asum = fabsf(al[0]) + fabsf(al[1]) + fabsf(al[2]) +
                     fabsf(al[3]) + fabsf(al[4]);
        int allz = __syncthreads_and(!valid || (asum == 0.0f));  // also fences sOut

        // ---- cooperative coalesced store: 10 threads cover one row's 160B ----
        #pragma unroll
        for (int k = 0; k < 10; k++) {
            int j = tid + THREADS * k;
            int rw = j / 10;
            int q = j - rw * 10;
            int r2 = base_row + rw;
            if (r2 < B)
                __stcs(outf4 + (size_t)r2 * F4_PER_ROW + w * 10 + q,
                       dyn[SOUT_IDX(rw, q)]);
        }

        if (allz) {
            texit = (w + 1) * W;
            asm volatile("cp.async.wait_group 0;" ::: "memory");  // drain before exit
            break;
        }
        if (w + 2 < NW) stage_window(sbase, x, base_row, B, w + 2, tid);
    }

    if (valid) g_texit[row] = texit;
}

// Proven R6 fill: zero [texit, T) per row, coalesced float4, grid (CHUNKS, B).
#define FILL_CHUNKS 4
#define FILL_THREADS 256

__global__ void __launch_bounds__(FILL_THREADS) fill_tail(float* __restrict__ out) {
    int row = blockIdx.y;
    int texit = g_texit[row];
    const int f4_per_row = F4_PER_ROW;               // 5120
    const int per_chunk = f4_per_row / FILL_CHUNKS;  // 1280
    int cstart = blockIdx.x * per_chunk;
    int cend = cstart + per_chunk;
    int fstart = texit * S / 4;                      // texit multiple of 8 -> exact
    int s = cstart > fstart ? cstart : fstart;

    float4* ob = reinterpret_cast<float4*>(out + (size_t)row * T_LEN * S);
    float4 z4 = make_float4(0.f, 0.f, 0.f, 0.f);
    for (int i = s + threadIdx.x; i < cend; i += FILL_THREADS) __stcs(&ob[i], z4);
}

extern "C" void kernel_launch(void* const* d_in, const int* in_sizes, int n_in,
                              void* d_out, int out_size) {
    const float4* x  = (const float4*)d_in[0];   // inputs (B, T, 4) fp32
    const float*  tk = (const float*)d_in[1];    // transition_kernel (5,5)
    const float*  ek = (const float*)d_in[2];    // emission_kernel (5,4)
    float* out = (float*)d_out;                  // alphas (B, T, 5) fp32

    int B = in_sizes[0] / (T_LEN * AL);
    if (B > MAXB) B = MAXB;

    cudaFuncSetAttribute(hmm_fwd, cudaFuncAttributeMaxDynamicSharedMemorySize,
                         SMEM_BYTES);

    int nFwd = (B + THREADS - 1) / THREADS;      // 16 CTAs for B=2048
    hmm_fwd<<<nFwd, THREADS, SMEM_BYTES>>>(x, tk, ek, out, B);

    dim3 fgrid(FILL_CHUNKS, B);
    fill_tail<<<fgrid, FILL_THREADS>>>(out);
}

// round 14
// speedup vs baseline: 1.1712x; 1.0643x over previous
#include <cuda_runtime.h>
#include <cuda_bf16.h>
#include <cstdint>
#include <math.h>

#define T_LEN 4096
#define S 5
#define AL 4
#define W 16                       // timesteps per window
#define NW (T_LEN / W)             // 256 windows
#define RPW 32                     // rows per warp (== threads per CTA)
#define NBUF 3                     // MUST cover in-flight set {w, w+1, w+2}
#define OUT_F4 (W * S / 4)         // 20 f4 output per row per window
#define F4_PER_ROW (T_LEN * S / 4) // 5120
#define MAXB 8192

__device__ int g_texit[MAXB];

// Static smem: sIn[3][32][17] f4 (pad 16->17: conflict-free), sOut[32][21] f4.
__device__ __forceinline__ unsigned int smem_u32(const void* p) {
    unsigned int a;
    asm("{ .reg .u64 t; cvta.to.shared.u64 t, %1; cvt.u32.u64 %0, t; }" : "=r"(a) : "l"(p));
    return a;
}

// Stage window w for this warp's 32 rows: 512 f4, 16 per lane.
// Fixed k: lanes cover 2 rows x 256B -> 4 lines per cp.async wavefront.
__device__ __forceinline__ void stage_window(unsigned int sin_base,
                                             const float4* __restrict__ x,
                                             int base_row, int B, int w, int lane) {
    int b = w % NBUF;
    #pragma unroll
    for (int k = 0; k < W; k++) {
        int i = lane + 32 * k;          // 0..511
        int rw = i >> 4;                 // row within warp
        int s = i & 15;                  // f4 within window
        int row = base_row + rw;
        if (row >= B) row = B - 1;       // duplicate load, never stored
        const float4* src = x + (size_t)row * T_LEN + w * W + s;
        unsigned int dst = sin_base + (unsigned int)(((b * RPW + rw) * 17 + s) * 16);
        asm volatile("cp.async.ca.shared.global [%0], [%1], 16;" :: "r"(dst), "l"(src));
    }
    asm volatile("cp.async.commit_group;");
}

__global__ void __launch_bounds__(RPW)
hmm_fwd(const float4* __restrict__ x,
        const float* __restrict__ tk,
        const float* __restrict__ ek,
        float* __restrict__ out, int B) {
    __shared__ float4 sIn[NBUF][RPW][17];
    __shared__ float4 sOut[RPW][21];
    __shared__ float sA[S * S];
    __shared__ float sB[S * AL];

    unsigned int sin_base = smem_u32(&sIn[0][0][0]);

    int lane = threadIdx.x;
    int base_row = blockIdx.x * RPW;

    // kick off input pipeline immediately (sIn only ever written by cp.async)
    stage_window(sin_base, x, base_row, B, 0, lane);
    stage_window(sin_base, x, base_row, B, 1, lane);

    if (lane < S) {
        float r[S];
        float m = -1e30f;
        #pragma unroll
        for (int j = 0; j < S; j++) { r[j] = tk[lane * S + j]; m = fmaxf(m, r[j]); }
        float s = 0.f;
        #pragma unroll
        for (int j = 0; j < S; j++) { r[j] = expf(r[j] - m); s += r[j]; }
        float inv = 1.0f / s;
        #pragma unroll
        for (int j = 0; j < S; j++) sA[lane * S + j] = r[j] * inv;

        float q[AL];
        m = -1e30f;
        #pragma unroll
        for (int j = 0; j < AL; j++) { q[j] = ek[lane * AL + j]; m = fmaxf(m, q[j]); }
        s = 0.f;
        #pragma unroll
        for (int j = 0; j < AL; j++) { q[j] = expf(q[j] - m); s += q[j]; }
        inv = 1.0f / s;
        #pragma unroll
        for (int j = 0; j < AL; j++) sB[lane * AL + j] = q[j] * inv;
    }
    __syncwarp();

    int row = base_row + lane;
    bool valid = row < B;

    float A_[S][S], Bm[S][AL];
    #pragma unroll
    for (int i = 0; i < S; i++) {
        #pragma unroll
        for (int j = 0; j < S; j++) A_[i][j] = sA[i * S + j];
        #pragma unroll
        for (int a = 0; a < AL; a++) Bm[i][a] = sB[i * AL + a];
    }

    float4* outf4 = reinterpret_cast<float4*>(out);

    float al[S];
    #pragma unroll
    for (int j = 0; j < S; j++) al[j] = 0.f;

    int texit = T_LEN;

    for (int w = 0; w < NW; w++) {
        // Prefetch w+2 into buffer (w+2)%3 — distinct from the buffers of
        // windows w and w+1 (NBUF=3), so issuing before the wait is safe.
        if (w + 2 < NW) {
            stage_window(sin_base, x, base_row, B, w + 2, lane);
            asm volatile("cp.async.wait_group 2;" ::: "memory");  // window w resident
        } else {
            asm volatile("cp.async.wait_group 0;" ::: "memory");
        }
        __syncwarp();                   // all lanes' window-w data visible

        const int b = w % NBUF;

        // ---- 16 steps for row `lane`, staged to sOut in output layout ----
        #pragma unroll
        for (int h = 0; h < 4; h++) {
            float st[4 * S];
            #pragma unroll
            for (int q = 0; q < 4; q++) {
                const int k = h * 4 + q;
                float4 v = sIn[b][lane][k];
                if (w == 0 && k == 0) {
                    // t = 0: alpha0 = [E(b,0,0), 0, 0, 0, 0]
                    al[0] = fmaf(Bm[0][3], v.w, fmaf(Bm[0][2], v.z,
                             fmaf(Bm[0][1], v.y, Bm[0][0] * v.x)));
                    #pragma unroll
                    for (int j = 1; j < S; j++) al[j] = 0.f;
                } else {
                    float e[S], ns[S];
                    #pragma unroll
                    for (int j = 0; j < S; j++)
                        e[j] = fmaf(Bm[j][3], v.w, fmaf(Bm[j][2], v.z,
                                 fmaf(Bm[j][1], v.y, Bm[j][0] * v.x)));
                    #pragma unroll
                    for (int j = 0; j < S; j++) {
                        float s01 = fmaf(al[1], A_[1][j], al[0] * A_[0][j]);
                        float s23 = fmaf(al[3], A_[3][j], al[2] * A_[2][j]);
                        float sm  = fmaf(al[4], A_[4][j], s01 + s23);
                        ns[j] = e[j] * sm;
                    }
                    #pragma unroll
                    for (int j = 0; j < S; j++) al[j] = ns[j];
                }
                #pragma unroll
                for (int j = 0; j < S; j++) st[q * S + j] = al[j];
            }
            // 4 steps x 5 states = 5 f4, step-major == global layout
            #pragma unroll
            for (int q = 0; q < 5; q++)
                sOut[lane][h * 5 + q] =
                    make_float4(st[q * 4 + 0], st[q * 4 + 1],
                                st[q * 4 + 2], st[q * 4 + 3]);
        }
        __syncwarp();                   // sOut visible to whole warp

        // ---- cooperative store: warp covers its 32 rows x 20 f4 ----
        #pragma unroll
        for (int k = 0; k < OUT_F4; k++) {
            int j = lane + 32 * k;       // 0..639
            int rw = j / OUT_F4;
            int q = j - rw * OUT_F4;
            int gr = base_row + rw;
            if (gr < B)
                __stcs(outf4 + (size_t)gr * F4_PER_ROW + w * OUT_F4 + q,
                       sOut[rw][q]);
        }

        float asum = fabsf(al[0]) + fabsf(al[1]) + fabsf(al[2]) +
                     fabsf(al[3]) + fabsf(al[4]);
        if (__all_sync(0xffffffffu, !valid || (asum == 0.0f))) {
            texit = (w + 1) * W;
            asm volatile("cp.async.wait_group 0;" ::: "memory");  // drain
            break;
        }
        __syncwarp();                   // sOut reads done before next overwrite
    }

    if (valid) g_texit[row] = texit;
}

// Proven fill: zero [texit, T) per row, coalesced float4, grid (CHUNKS, B).
#define FILL_CHUNKS 4
#define FILL_THREADS 256

__global__ void __launch_bounds__(FILL_THREADS) fill_tail(float* __restrict__ out) {
    int row = blockIdx.y;
    int texit = g_texit[row];
    const int per_chunk = F4_PER_ROW / FILL_CHUNKS;  // 1280
    int cstart = blockIdx.x * per_chunk;
    int cend = cstart + per_chunk;
    int fstart = texit * S / 4;                      // texit multiple of 16 -> exact
    int s = cstart > fstart ? cstart : fstart;

    float4* ob = reinterpret_cast<float4*>(out + (size_t)row * T_LEN * S);
    float4 z4 = make_float4(0.f, 0.f, 0.f, 0.f);
    for (int i = s + threadIdx.x; i < cend; i += FILL_THREADS) __stcs(&ob[i], z4);
}

extern "C" void kernel_launch(void* const* d_in, const int* in_sizes, int n_in,
                              void* d_out, int out_size) {
    const float4* x  = (const float4*)d_in[0];   // inputs (B, T, 4) fp32
    const float*  tk = (const float*)d_in[1];    // transition_kernel (5,5)
    const float*  ek = (const float*)d_in[2];    // emission_kernel (5,4)
    float* out = (float*)d_out;                  // alphas (B, T, 5) fp32

    int B = in_sizes[0] / (T_LEN * AL);
    if (B > MAXB) B = MAXB;

    int nFwd = (B + RPW - 1) / RPW;              // 64 CTAs for B=2048
    hmm_fwd<<<nFwd, RPW>>>(x, tk, ek, out, B);

    dim3 fgrid(FILL_CHUNKS, B);
    fill_tail<<<fgrid, FILL_THREADS>>>(out);
}